// round 4
// baseline (speedup 1.0000x reference)
#include <cuda_runtime.h>
#include <cstdint>

#define TILE_E     64
#define KDIM       256
#define NDIM       64
#define THREADS    256
#define NKP        (KDIM / 2)          // 128 k-pairs

#define X_STRIDE_B 1040                // 260 floats: 16B-aligned rows, stride-conflict-free
#define X_BUF_B    (TILE_E * X_STRIDE_B)        // 66560
#define WP_STRIDE_B 528                // 64 ull + 2 pad, 16B multiple
#define WP_OFF     0
#define X0_OFF     (NKP * WP_STRIDE_B)          // 67584
#define X1_OFF     (X0_OFF + X_BUF_B)
#define SMEM_TOTAL (X1_OFF + X_BUF_B)           // 200704

typedef unsigned long long ull;

__device__ int g_idx_is32;   // 1 if edge_index is int32, 0 if int64

__device__ __forceinline__ ull pack2(float a, float b) {
    ull r; asm("mov.b64 %0, {%1, %2};" : "=l"(r) : "f"(a), "f"(b)); return r;
}
__device__ __forceinline__ void fma2(ull& d, ull a, ull b) {
    asm("fma.rn.f32x2 %0, %1, %2, %0;" : "+l"(d) : "l"(a), "l"(b));
}
__device__ __forceinline__ void unpack2(ull v, float& lo, float& hi) {
    asm("mov.b64 {%0, %1}, %2;" : "=f"(lo), "=f"(hi) : "l"(v));
}
__device__ __forceinline__ unsigned sm2u32(const void* p) {
    unsigned a;
    asm("{ .reg .u64 t; cvta.to.shared.u64 t, %1; cvt.u32.u64 %0, t; }" : "=r"(a) : "l"(p));
    return a;
}
__device__ __forceinline__ void cp16(unsigned dst, const void* src) {
    asm volatile("cp.async.cg.shared.global [%0], [%1], 16;" :: "r"(dst), "l"(src) : "memory");
}
#define CP_COMMIT() asm volatile("cp.async.commit_group;" ::: "memory")
#define CP_WAIT1()  asm volatile("cp.async.wait_group 1;" ::: "memory")

// Probe: int64 ids < 2^31 have zero odd 32-bit words; int32 data has node ids there.
__global__ void probe_idx_dtype(const int* __restrict__ w, int n_words) {
    int any = 0;
    for (int i = threadIdx.x * 2 + 1; i < n_words && i < 8192; i += 64) any |= w[i];
    any = __any_sync(0xffffffffu, any != 0);
    if (threadIdx.x == 0) g_idx_is32 = any ? 1 : 0;
}

// Issue the async gather of tile `tile` into xbuf (u32 smem addr). 16 LDGSTS/thread.
__device__ __forceinline__ void issue_gather(const float* __restrict__ node_emb,
                                             const void* __restrict__ edge_index,
                                             int is32, unsigned xbuf,
                                             int tile, int E, int n_nodes, int tid)
{
    const int r    = tid >> 1;          // 0..127 : (e, half)
    const int e    = r & (TILE_E - 1);
    const int half = r >> 6;
    int ge = tile * TILE_E + e;
    if (ge >= E) ge = E - 1;            // duplicate-gather tail; output is guarded
    long long node;
    if (is32) node = ((const int*)edge_index)[(long long)half * E + ge];
    else      node = ((const long long*)edge_index)[(long long)half * E + ge];
    if (node < 0) node = 0;
    if (node >= n_nodes) node = n_nodes - 1;

    const float* src = node_emb + node * 128 + (tid & 1) * 64;   // this thread's 64-float slab
    unsigned     dst = xbuf + e * X_STRIDE_B + half * 512 + (tid & 1) * 256;
    #pragma unroll
    for (int q = 0; q < 16; ++q)
        cp16(dst + q * 16, src + q * 4);
    CP_COMMIT();
}

__global__ __launch_bounds__(THREADS, 1)
void edge_mlp_pipe(const float* __restrict__ node_emb,
                   const void*  __restrict__ edge_index,
                   const float* __restrict__ W1,
                   const float* __restrict__ b1,
                   const float* __restrict__ W2,
                   const float* __restrict__ b2,
                   float* __restrict__ out,
                   int E, int n_nodes, int ntiles)
{
    extern __shared__ unsigned char sm[];
    __shared__ float2 bw[NDIM];         // (b1[j], W2[j])
    __shared__ float  b2s;

    const int tid = threadIdx.x;
    const int is32 = g_idx_is32;

    // ---- stage WP once: WP[kp][j] = (W1[2kp][j], W1[2kp+1][j]) ----
    {
        const int kp = tid >> 1;                 // 0..127
        const int j0 = (tid & 1) * 32;
        const float* w0 = W1 + (2 * kp)     * NDIM;
        const float* w1 = W1 + (2 * kp + 1) * NDIM;
        ull* row = (ull*)(sm + WP_OFF + kp * WP_STRIDE_B);
        #pragma unroll 8
        for (int jj = 0; jj < 32; ++jj) {
            const int j = j0 + jj;
            row[j] = pack2(w0[j], w1[j]);
        }
        if (tid < NDIM) bw[tid] = make_float2(b1[tid], W2[tid]);
        if (tid == NDIM) b2s = b2[0];
    }

    const int tx = tid & 15;   // col group: j = tx*4 .. tx*4+3
    const int ey = tid >> 4;   // edge group: e = ey*4 .. ey*4+3

    const unsigned x_u32[2] = { sm2u32(sm + X0_OFF), sm2u32(sm + X1_OFF) };
    const unsigned char* xbase[2] = { sm + X0_OFF + ey * 4 * X_STRIDE_B,
                                      sm + X1_OFF + ey * 4 * X_STRIDE_B };
    const unsigned char* wpbase = sm + WP_OFF + tx * 32;

    // prologue: gather first tile
    int tile = blockIdx.x;
    if (tile < ntiles)
        issue_gather(node_emb, edge_index, is32, x_u32[0], tile, E, n_nodes, tid);
    __syncthreads();   // WP/bw staged (also joins prologue gather issue order)

    float b1v[4], w2v[4];
    #pragma unroll
    for (int j = 0; j < 4; ++j) {
        const float2 c = bw[tx * 4 + j];
        b1v[j] = c.x; w2v[j] = c.y;
    }
    const float bb = b2s;

    int cur = 0;
    for (; tile < ntiles; tile += gridDim.x, cur ^= 1) {
        // prefetch next tile into the other buffer
        const int tn = tile + gridDim.x;
        if (tn < ntiles)
            issue_gather(node_emb, edge_index, is32, x_u32[cur ^ 1], tn, E, n_nodes, tid);
        else
            CP_COMMIT();                 // keep group accounting uniform
        CP_WAIT1();                      // current tile's gather complete (newest may fly)
        __syncthreads();                 // publish buffer to all warps

        // ---- GEMM: 64 edges x 64 cols, thread = 4e x 4c, f32x2 over k-pairs ----
        ull acc[4][4];
        #pragma unroll
        for (int i = 0; i < 4; ++i)
            #pragma unroll
            for (int j = 0; j < 4; ++j) acc[i][j] = 0ULL;

        const unsigned char* xb = xbase[cur];
        #pragma unroll 4
        for (int kp = 0; kp < NKP; ++kp) {
            ull xa[4];
            #pragma unroll
            for (int i = 0; i < 4; ++i)
                xa[i] = *(const ull*)(xb + i * X_STRIDE_B + kp * 8);
            const ulonglong2 wA = *(const ulonglong2*)(wpbase + kp * WP_STRIDE_B);
            const ulonglong2 wB = *(const ulonglong2*)(wpbase + kp * WP_STRIDE_B + 16);
            #pragma unroll
            for (int i = 0; i < 4; ++i) {
                fma2(acc[i][0], xa[i], wA.x);
                fma2(acc[i][1], xa[i], wA.y);
                fma2(acc[i][2], xa[i], wB.x);
                fma2(acc[i][3], xa[i], wB.y);
            }
        }

        // ---- epilogue: h = relu(sum_k + b1); logit = h . W2 + b2 ----
        float p[4] = {0.f, 0.f, 0.f, 0.f};
        #pragma unroll
        for (int i = 0; i < 4; ++i)
            #pragma unroll
            for (int j = 0; j < 4; ++j) {
                float lo, hi; unpack2(acc[i][j], lo, hi);
                float h = lo + hi + b1v[j];
                h = fmaxf(h, 0.f);
                p[i] = fmaf(h, w2v[j], p[i]);
            }
        #pragma unroll
        for (int off = 8; off; off >>= 1)
            #pragma unroll
            for (int i = 0; i < 4; ++i)
                p[i] += __shfl_xor_sync(0xffffffffu, p[i], off);

        if (tx == 0) {
            const int e0 = tile * TILE_E + ey * 4;
            if (e0 + 3 < E) {
                *(float4*)(out + e0) = make_float4(p[0] + bb, p[1] + bb, p[2] + bb, p[3] + bb);
            } else {
                #pragma unroll
                for (int i = 0; i < 4; ++i)
                    if (e0 + i < E) out[e0 + i] = p[i] + bb;
            }
        }
        __syncthreads();   // all reads of buf[cur] done before it is refilled
    }
}

extern "C" void kernel_launch(void* const* d_in, const int* in_sizes, int n_in,
                              void* d_out, int out_size)
{
    const float* node_emb   = (const float*)d_in[0];
    const void*  edge_index = d_in[1];
    const float* W1         = (const float*)d_in[2];
    const float* b1         = (const float*)d_in[3];
    const float* W2         = (const float*)d_in[4];
    const float* b2         = (const float*)d_in[5];
    float*       out        = (float*)d_out;

    const int E       = out_size;              // one logit per edge
    const int n_nodes = in_sizes[0] / 128;
    const int ntiles  = (E + TILE_E - 1) / TILE_E;   // 12500

    probe_idx_dtype<<<1, 32>>>((const int*)edge_index, 2 * E);

    int nsm = 148;
    cudaDeviceGetAttribute(&nsm, cudaDevAttrMultiProcessorCount, 0);
    const int grid = nsm < ntiles ? nsm : ntiles;

    cudaFuncSetAttribute(edge_mlp_pipe,
                         cudaFuncAttributeMaxDynamicSharedMemorySize, SMEM_TOTAL);

    edge_mlp_pipe<<<grid, THREADS, SMEM_TOTAL>>>(node_emb, edge_index, W1, b1, W2, b2,
                                                 out, E, n_nodes, ntiles);
}

// round 5
// speedup vs baseline: 1.3096x; 1.3096x over previous
#include <cuda_runtime.h>
#include <cstdint>

#define TILE_E     64
#define KDIM       256
#define NDIM       64
#define THREADS    256
#define NKP2       (KDIM / 4)                   // 64 iterations of 4 k

#define ROW_B      1040                         // 1024 + 16 pad (odd 16B multiple)
#define WPT_OFF    0
#define WPT_B      (NKP2 * ROW_B)               // 66560
#define X0_OFF     WPT_B
#define X_BUF_B    (TILE_E * ROW_B)             // 66560
#define X1_OFF     (X0_OFF + X_BUF_B)
#define SMEM_TOTAL (X1_OFF + X_BUF_B)           // 199680

typedef unsigned long long ull;

__device__ int g_idx_is32;   // 1 if edge_index is int32, 0 if int64

__device__ __forceinline__ ull pack2(float a, float b) {
    ull r; asm("mov.b64 %0, {%1, %2};" : "=l"(r) : "f"(a), "f"(b)); return r;
}
__device__ __forceinline__ void fma2(ull& d, ull a, ull b) {
    asm("fma.rn.f32x2 %0, %1, %2, %0;" : "+l"(d) : "l"(a), "l"(b));
}
__device__ __forceinline__ void unpack2(ull v, float& lo, float& hi) {
    asm("mov.b64 {%0, %1}, %2;" : "=f"(lo), "=f"(hi) : "l"(v));
}
__device__ __forceinline__ unsigned sm2u32(const void* p) {
    unsigned a;
    asm("{ .reg .u64 t; cvta.to.shared.u64 t, %1; cvt.u32.u64 %0, t; }" : "=r"(a) : "l"(p));
    return a;
}
__device__ __forceinline__ void cp16(unsigned dst, const void* src) {
    asm volatile("cp.async.cg.shared.global [%0], [%1], 16;" :: "r"(dst), "l"(src) : "memory");
}
#define CP_COMMIT() asm volatile("cp.async.commit_group;" ::: "memory")
#define CP_WAIT1()  asm volatile("cp.async.wait_group 1;" ::: "memory")

// Probe: int64 ids < 2^31 have zero odd 32-bit words; int32 data has node ids there.
__global__ void probe_idx_dtype(const int* __restrict__ w, int n_words) {
    int any = 0;
    for (int i = threadIdx.x * 2 + 1; i < n_words && i < 8192; i += 64) any |= w[i];
    any = __any_sync(0xffffffffu, any != 0);
    if (threadIdx.x == 0) g_idx_is32 = any ? 1 : 0;
}

// Async gather of tile `tile` into xbuf: 16 LDGSTS.16 per thread.
__device__ __forceinline__ void issue_gather(const float* __restrict__ node_emb,
                                             const void* __restrict__ edge_index,
                                             int is32, unsigned xbuf,
                                             int tile, int E, int n_nodes, int tid)
{
    const int r    = tid >> 1;                  // 0..127 : (e, half)
    const int e    = r & (TILE_E - 1);
    const int half = r >> 6;
    int ge = tile * TILE_E + e;
    if (ge >= E) ge = E - 1;                    // duplicate-gather tail; output guarded
    long long node;
    if (is32) node = ((const int*)edge_index)[(long long)half * E + ge];
    else      node = ((const long long*)edge_index)[(long long)half * E + ge];
    if (node < 0) node = 0;
    if (node >= n_nodes) node = n_nodes - 1;

    const float* src = node_emb + node * 128 + (tid & 1) * 64;
    unsigned     dst = xbuf + e * ROW_B + half * 512 + (tid & 1) * 256;
    #pragma unroll
    for (int q = 0; q < 16; ++q)
        cp16(dst + q * 16, src + q * 4);
    CP_COMMIT();
}

__global__ __launch_bounds__(THREADS, 1)
void edge_mlp_v5(const float* __restrict__ node_emb,
                 const void*  __restrict__ edge_index,
                 const float* __restrict__ W1,
                 const float* __restrict__ b1,
                 const float* __restrict__ W2,
                 const float* __restrict__ b2,
                 float* __restrict__ out,
                 int E, int n_nodes, int ntiles)
{
    extern __shared__ unsigned char sm[];
    __shared__ float2 bw[NDIM];                 // (b1[j], W2[j])
    __shared__ float  b2s;

    const int tid  = threadIdx.x;
    const int is32 = g_idx_is32;

    // ---- stage WPT2 once: entry(kp2, jj, tx) = 4 k-values of col j=tx*4+jj, 2 ull ----
    {
        const int tx_s = tid & 15;
        const int jj_s = (tid >> 4) & 3;
        const int kg   = tid >> 6;              // 0..3
        const int j    = tx_s * 4 + jj_s;
        for (int kp2 = kg; kp2 < NKP2; kp2 += 4) {
            const int k0 = kp2 * 4;
            const float a0 = W1[(k0 + 0) * NDIM + j];
            const float a1 = W1[(k0 + 1) * NDIM + j];
            const float a2 = W1[(k0 + 2) * NDIM + j];
            const float a3 = W1[(k0 + 3) * NDIM + j];
            ulonglong2 t;
            t.x = pack2(a0, a1);
            t.y = pack2(a2, a3);
            *(ulonglong2*)(sm + WPT_OFF + kp2 * ROW_B + jj_s * 256 + tx_s * 16) = t;
        }
        if (tid < NDIM) bw[tid] = make_float2(b1[tid], W2[tid]);
        if (tid == NDIM) b2s = b2[0];
    }

    const int tx = tid & 15;                    // cols tx*4 .. tx*4+3
    const int ey = tid >> 4;                    // edges ey*4 .. ey*4+3

    const unsigned x_u32[2] = { sm2u32(sm + X0_OFF), sm2u32(sm + X1_OFF) };
    const unsigned char* xbase[2] = { sm + X0_OFF + ey * 4 * ROW_B,
                                      sm + X1_OFF + ey * 4 * ROW_B };
    const unsigned char* wbase = sm + WPT_OFF + tx * 16;

    // prologue: gather first tile
    int tile = blockIdx.x;
    if (tile < ntiles)
        issue_gather(node_emb, edge_index, is32, x_u32[0], tile, E, n_nodes, tid);
    __syncthreads();

    float b1v[4], w2v[4];
    #pragma unroll
    for (int j = 0; j < 4; ++j) {
        const float2 c = bw[tx * 4 + j];
        b1v[j] = c.x; w2v[j] = c.y;
    }
    const float bb = b2s;

    int cur = 0;
    for (; tile < ntiles; tile += gridDim.x, cur ^= 1) {
        const int tn = tile + gridDim.x;
        if (tn < ntiles)
            issue_gather(node_emb, edge_index, is32, x_u32[cur ^ 1], tn, E, n_nodes, tid);
        else
            CP_COMMIT();
        CP_WAIT1();
        __syncthreads();

        // ---- GEMM: 64e x 64c, thread = 4e x 4c, 4 k per iteration ----
        ull acc[4][4];
        #pragma unroll
        for (int i = 0; i < 4; ++i)
            #pragma unroll
            for (int j = 0; j < 4; ++j) acc[i][j] = 0ULL;

        const unsigned char* xb = xbase[cur];
        #pragma unroll 4
        for (int kp2 = 0; kp2 < NKP2; ++kp2) {
            ulonglong2 xv[4];
            #pragma unroll
            for (int i = 0; i < 4; ++i)
                xv[i] = *(const ulonglong2*)(xb + i * ROW_B + kp2 * 16);
            ulonglong2 wv[4];
            #pragma unroll
            for (int j = 0; j < 4; ++j)
                wv[j] = *(const ulonglong2*)(wbase + kp2 * ROW_B + j * 256);
            #pragma unroll
            for (int i = 0; i < 4; ++i)
                #pragma unroll
                for (int j = 0; j < 4; ++j) {
                    fma2(acc[i][j], xv[i].x, wv[j].x);   // k, k+1
                    fma2(acc[i][j], xv[i].y, wv[j].y);   // k+2, k+3
                }
        }

        // ---- epilogue: h = relu(lo+hi + b1); logit = h . W2 + b2 ----
        float p[4] = {0.f, 0.f, 0.f, 0.f};
        #pragma unroll
        for (int i = 0; i < 4; ++i)
            #pragma unroll
            for (int j = 0; j < 4; ++j) {
                float lo, hi; unpack2(acc[i][j], lo, hi);
                float h = lo + hi + b1v[j];
                h = fmaxf(h, 0.f);
                p[i] = fmaf(h, w2v[j], p[i]);
            }
        #pragma unroll
        for (int off = 8; off; off >>= 1)
            #pragma unroll
            for (int i = 0; i < 4; ++i)
                p[i] += __shfl_xor_sync(0xffffffffu, p[i], off);

        if (tx == 0) {
            const int e0 = tile * TILE_E + ey * 4;
            if (e0 + 3 < E) {
                *(float4*)(out + e0) = make_float4(p[0] + bb, p[1] + bb, p[2] + bb, p[3] + bb);
            } else {
                #pragma unroll
                for (int i = 0; i < 4; ++i)
                    if (e0 + i < E) out[e0 + i] = p[i] + bb;
            }
        }
        __syncthreads();   // all reads of buf[cur] done before refill
    }
}

extern "C" void kernel_launch(void* const* d_in, const int* in_sizes, int n_in,
                              void* d_out, int out_size)
{
    const float* node_emb   = (const float*)d_in[0];
    const void*  edge_index = d_in[1];
    const float* W1         = (const float*)d_in[2];
    const float* b1         = (const float*)d_in[3];
    const float* W2         = (const float*)d_in[4];
    const float* b2         = (const float*)d_in[5];
    float*       out        = (float*)d_out;

    const int E       = out_size;
    const int n_nodes = in_sizes[0] / 128;
    const int ntiles  = (E + TILE_E - 1) / TILE_E;   // 12500

    probe_idx_dtype<<<1, 32>>>((const int*)edge_index, 2 * E);

    int nsm = 148;
    cudaDeviceGetAttribute(&nsm, cudaDevAttrMultiProcessorCount, 0);
    const int grid = nsm < ntiles ? nsm : ntiles;

    cudaFuncSetAttribute(edge_mlp_v5,
                         cudaFuncAttributeMaxDynamicSharedMemorySize, SMEM_TOTAL);

    edge_mlp_v5<<<grid, THREADS, SMEM_TOTAL>>>(node_emb, edge_index, W1, b1, W2, b2,
                                               out, E, n_nodes, ntiles);
}

// round 6
// speedup vs baseline: 3.3368x; 2.5479x over previous
#include <cuda_runtime.h>
#include <cstdint>

#define TILE_E    64
#define KDIM      256
#define NDIM      64
#define THREADS   256
#define ROW_B     1040                    // bytes per edge row: 256 floats + 16B pad
#define A_BUF_B   (TILE_E * ROW_B)        // 66560
#define B_OFF     (2 * A_BUF_B)           // 133120
#define B_BYTES   65536
#define SMEM_TOTAL (B_OFF + B_BYTES)      // 198656

__device__ int g_idx_is32;   // 1 if edge_index is int32, 0 if int64

__device__ __forceinline__ unsigned sm2u32(const void* p) {
    unsigned a;
    asm("{ .reg .u64 t; cvta.to.shared.u64 t, %1; cvt.u32.u64 %0, t; }" : "=r"(a) : "l"(p));
    return a;
}
__device__ __forceinline__ unsigned f2tf32(float f) {
    unsigned r; asm("cvt.rna.tf32.f32 %0, %1;" : "=r"(r) : "f"(f)); return r;
}
__device__ __forceinline__ void cp16(unsigned dst, const void* src) {
    asm volatile("cp.async.cg.shared.global [%0], [%1], 16;" :: "r"(dst), "l"(src) : "memory");
}
#define CP_COMMIT() asm volatile("cp.async.commit_group;" ::: "memory")
#define CP_WAIT1()  asm volatile("cp.async.wait_group 1;" ::: "memory")

// D += A(16x8) * B(8x8), tf32 -> f32
__device__ __forceinline__ void mma_tf32(float* c, unsigned a0, unsigned a1,
                                         unsigned a2, unsigned a3,
                                         unsigned b0, unsigned b1) {
    asm volatile(
        "mma.sync.aligned.m16n8k8.row.col.f32.tf32.tf32.f32 "
        "{%0,%1,%2,%3}, {%4,%5,%6,%7}, {%8,%9}, {%0,%1,%2,%3};"
        : "+f"(c[0]), "+f"(c[1]), "+f"(c[2]), "+f"(c[3])
        : "r"(a0), "r"(a1), "r"(a2), "r"(a3), "r"(b0), "r"(b1));
}

// Probe: int64 ids < 2^31 have zero odd 32-bit words; int32 data has node ids there.
__global__ void probe_idx_dtype(const int* __restrict__ w, int n_words) {
    int any = 0;
    for (int i = threadIdx.x * 2 + 1; i < n_words && i < 8192; i += 64) any |= w[i];
    any = __any_sync(0xffffffffu, any != 0);
    if (threadIdx.x == 0) g_idx_is32 = any ? 1 : 0;
}

// Async gather of tile `tile` into xbuf (k-contiguous fp32 rows): 16 LDGSTS.16/thread.
__device__ __forceinline__ void issue_gather(const float* __restrict__ node_emb,
                                             const void* __restrict__ edge_index,
                                             int is32, unsigned xbuf,
                                             int tile, int E, int n_nodes, int tid)
{
    const int r    = tid >> 1;                  // 0..127 : (e, half)
    const int e    = r & (TILE_E - 1);
    const int half = r >> 6;
    int ge = tile * TILE_E + e;
    if (ge >= E) ge = E - 1;                    // duplicate-gather tail; output guarded
    long long node;
    if (is32) node = ((const int*)edge_index)[(long long)half * E + ge];
    else      node = ((const long long*)edge_index)[(long long)half * E + ge];
    if (node < 0) node = 0;
    if (node >= n_nodes) node = n_nodes - 1;

    const float* src = node_emb + node * 128 + (tid & 1) * 64;
    unsigned     dst = xbuf + e * ROW_B + half * 512 + (tid & 1) * 256;
    #pragma unroll
    for (int q = 0; q < 16; ++q)
        cp16(dst + q * 16, src + q * 4);
    CP_COMMIT();
}

__global__ __launch_bounds__(THREADS, 1)
void edge_mlp_mma(const float* __restrict__ node_emb,
                  const void*  __restrict__ edge_index,
                  const float* __restrict__ W1,
                  const float* __restrict__ b1,
                  const float* __restrict__ W2,
                  const float* __restrict__ b2,
                  float* __restrict__ out,
                  int E, int n_nodes, int ntiles)
{
    extern __shared__ unsigned char sm[];
    __shared__ float sPart[2][TILE_E];

    const int tid  = threadIdx.x;
    const int wid  = tid >> 5;
    const int lane = tid & 31;
    const int mw   = wid & 3;        // m-warp: edges mw*16 .. mw*16+15
    const int nw   = wid >> 2;       // n-warp: cols  nw*32 .. nw*32+31
    const int g    = lane >> 2;      // group id 0..7
    const int t    = lane & 3;
    const int is32 = g_idx_is32;

    // ---- stage B = W1 in m16n8k8 fragment order, tf32 (once) ----
    // entry idx=(ks,nw,fp,lane): uint4 = (b0_f, b1_f, b0_f', b1_f') for frags f=2fp, f'=2fp+1
    #pragma unroll
    for (int i = 0; i < 16; ++i) {
        const int idx = tid + i * 256;            // 0..4095
        const int l   = idx & 31;
        const int fp  = (idx >> 5) & 1;
        const int nwi = (idx >> 6) & 1;
        const int ks  = idx >> 7;
        const int gg  = l >> 2, tt = l & 3;
        const int k0  = ks * 8 + tt;
        const int n0  = nwi * 32 + fp * 16 + gg;
        uint4 v;
        v.x = f2tf32(W1[k0 * NDIM + n0]);
        v.y = f2tf32(W1[(k0 + 4) * NDIM + n0]);
        v.z = f2tf32(W1[k0 * NDIM + n0 + 8]);
        v.w = f2tf32(W1[(k0 + 4) * NDIM + n0 + 8]);
        *(uint4*)(sm + B_OFF + idx * 16) = v;
    }

    // ---- per-thread epilogue constants: cols j0=nw*32+f*8+2t, j1=j0+1 ----
    float b1a[4], w2a[4], b1b[4], w2b[4];
    #pragma unroll
    for (int f = 0; f < 4; ++f) {
        const int j0 = nw * 32 + f * 8 + 2 * t;
        b1a[f] = b1[j0];     w2a[f] = W2[j0];
        b1b[f] = b1[j0 + 1]; w2b[f] = W2[j0 + 1];
    }
    const float bb = b2[0];

    const unsigned x_u32[2] = { sm2u32(sm), sm2u32(sm + A_BUF_B) };
    // A-frag row pointers (within a buffer): rows mw*16+g and +8, col byte t*4
    const unsigned char* a0base = sm + (mw * 16 + g) * ROW_B + t * 4;
    const unsigned char* bP     = sm + B_OFF + nw * 1024 + lane * 16;

    int tile = blockIdx.x;
    if (tile < ntiles)
        issue_gather(node_emb, edge_index, is32, x_u32[0], tile, E, n_nodes, tid);
    __syncthreads();   // B staged + prologue ordering

    int cur = 0;
    for (; tile < ntiles; tile += gridDim.x, cur ^= 1) {
        const int tn = tile + gridDim.x;
        if (tn < ntiles)
            issue_gather(node_emb, edge_index, is32, x_u32[cur ^ 1], tn, E, n_nodes, tid);
        else
            CP_COMMIT();
        CP_WAIT1();                  // current tile's gather complete
        __syncthreads();

        // ---- GEMM: warp m16 x n32, K=256 in 32 k8-steps ----
        float acc[4][4];
        #pragma unroll
        for (int f = 0; f < 4; ++f)
            #pragma unroll
            for (int c = 0; c < 4; ++c) acc[f][c] = 0.f;

        const unsigned char* aR0 = a0base + cur * A_BUF_B;
        const unsigned char* aR1 = aR0 + 8 * ROW_B;
        #pragma unroll 4
        for (int ks = 0; ks < KDIM / 8; ++ks) {
            const unsigned a0 = *(const unsigned*)(aR0 + ks * 32);
            const unsigned a2 = *(const unsigned*)(aR0 + ks * 32 + 16);
            const unsigned a1 = *(const unsigned*)(aR1 + ks * 32);
            const unsigned a3 = *(const unsigned*)(aR1 + ks * 32 + 16);
            const uint4 B0 = *(const uint4*)(bP + ks * 2048);
            const uint4 B1 = *(const uint4*)(bP + ks * 2048 + 512);
            mma_tf32(acc[0], a0, a1, a2, a3, B0.x, B0.y);
            mma_tf32(acc[1], a0, a1, a2, a3, B0.z, B0.w);
            mma_tf32(acc[2], a0, a1, a2, a3, B1.x, B1.y);
            mma_tf32(acc[3], a0, a1, a2, a3, B1.z, B1.w);
        }

        // ---- epilogue: relu(+b1) . W2, reduce over t-lanes, combine n-warps ----
        float pg = 0.f, pg8 = 0.f;
        #pragma unroll
        for (int f = 0; f < 4; ++f) {
            pg  = fmaf(fmaxf(acc[f][0] + b1a[f], 0.f), w2a[f], pg);
            pg  = fmaf(fmaxf(acc[f][1] + b1b[f], 0.f), w2b[f], pg);
            pg8 = fmaf(fmaxf(acc[f][2] + b1a[f], 0.f), w2a[f], pg8);
            pg8 = fmaf(fmaxf(acc[f][3] + b1b[f], 0.f), w2b[f], pg8);
        }
        pg  += __shfl_xor_sync(0xffffffffu, pg, 1);
        pg  += __shfl_xor_sync(0xffffffffu, pg, 2);
        pg8 += __shfl_xor_sync(0xffffffffu, pg8, 1);
        pg8 += __shfl_xor_sync(0xffffffffu, pg8, 2);
        if (t == 0) {
            sPart[nw][mw * 16 + g]     = pg;
            sPart[nw][mw * 16 + g + 8] = pg8;
        }
        __syncthreads();
        if (tid < TILE_E) {
            const int e = tile * TILE_E + tid;
            if (e < E) out[e] = sPart[0][tid] + sPart[1][tid] + bb;
        }
        __syncthreads();   // sPart consumed + all A-buffer reads done before refill
    }
}

extern "C" void kernel_launch(void* const* d_in, const int* in_sizes, int n_in,
                              void* d_out, int out_size)
{
    const float* node_emb   = (const float*)d_in[0];
    const void*  edge_index = d_in[1];
    const float* W1         = (const float*)d_in[2];
    const float* b1         = (const float*)d_in[3];
    const float* W2         = (const float*)d_in[4];
    const float* b2         = (const float*)d_in[5];
    float*       out        = (float*)d_out;

    const int E       = out_size;
    const int n_nodes = in_sizes[0] / 128;
    const int ntiles  = (E + TILE_E - 1) / TILE_E;   // 12500

    probe_idx_dtype<<<1, 32>>>((const int*)edge_index, 2 * E);

    int nsm = 148;
    cudaDeviceGetAttribute(&nsm, cudaDevAttrMultiProcessorCount, 0);
    const int grid = nsm < ntiles ? nsm : ntiles;

    cudaFuncSetAttribute(edge_mlp_mma,
                         cudaFuncAttributeMaxDynamicSharedMemorySize, SMEM_TOTAL);

    edge_mlp_mma<<<grid, THREADS, SMEM_TOTAL>>>(node_emb, edge_index, W1, b1, W2, b2,
                                                out, E, n_nodes, ntiles);
}